// round 15
// baseline (speedup 1.0000x reference)
#include <cuda_runtime.h>
#include <cuda_bf16.h>
#include <math.h>
#include <stdint.h>

// ---------------- Problem constants ----------------
#define BATCH   4
#define SEQ     2048
#define ROWS    (BATCH*SEQ)      // 8192
#define DIMS    1024
#define STATE   2048             // 2*DIMS
#define NTOT    (4*STATE)        // 8192 logical GEMM1 columns [K | u/gin 8-blocked | gout]
#define TCH     128              // scan chunk length
#define NCH     (SEQ/TCH)        // 16 chunks

// ---------------- Scratch (device globals; no allocation allowed) ----------------
__device__ __nv_bfloat16 g_xn[(size_t)ROWS*DIMS];       // 16MB  normalized input (bf16)
__device__ __nv_bfloat16 g_WT[(size_t)NTOT*DIMS];       // 16MB  packed weights^T bf16
__device__ __nv_bfloat16 g_WoutT[(size_t)DIMS*STATE];   // 4MB   Wout^T as [n,k] bf16
__device__ __nv_bfloat16 g_CD [(size_t)ROWS*STATE];     // 32MB  d = 1-sig(K) bf16
__device__ __nv_bfloat16 g_CU2[(size_t)ROWS*STATE];     // 32MB  u2 = u*sig(gin) bf16
__device__ __nv_bfloat16 g_CGO[(size_t)ROWS*STATE];     // 32MB  sig(gout) bf16
__device__ __nv_bfloat16 g_out1[(size_t)ROWS*STATE];    // 32MB  h*sig(gout) bf16
__device__ float g_chA[BATCH*NCH*STATE];
__device__ float g_chB[BATCH*NCH*STATE];
__device__ float g_hin[BATCH*NCH*STATE];

// ---------------- Helpers ----------------
__device__ __forceinline__ uint32_t smem_u32(const void* p) {
    uint32_t a;
    asm("{ .reg .u64 t; cvta.to.shared.u64 t, %1; cvt.u32.u64 %0, t; }" : "=r"(a) : "l"(p));
    return a;
}
__device__ __forceinline__ void cp16(uint32_t dst, const void* src) {
    asm volatile("cp.async.cg.shared.global [%0], [%1], 16;" :: "r"(dst), "l"(src) : "memory");
}
#define CP_COMMIT() asm volatile("cp.async.commit_group;" ::: "memory")

__device__ __forceinline__ void ldm_x4(uint32_t* r, uint32_t addr) {
    asm volatile("ldmatrix.sync.aligned.m8n8.x4.shared.b16 {%0,%1,%2,%3}, [%4];"
                 : "=r"(r[0]), "=r"(r[1]), "=r"(r[2]), "=r"(r[3]) : "r"(addr));
}
__device__ __forceinline__ void mma_bf16(float* c, const uint32_t* a,
                                         uint32_t b0, uint32_t b1) {
    asm volatile(
        "mma.sync.aligned.m16n8k16.row.col.f32.bf16.bf16.f32 "
        "{%0,%1,%2,%3},{%4,%5,%6,%7},{%8,%9},{%0,%1,%2,%3};"
        : "+f"(c[0]), "+f"(c[1]), "+f"(c[2]), "+f"(c[3])
        : "r"(a[0]), "r"(a[1]), "r"(a[2]), "r"(a[3]), "r"(b0), "r"(b1));
}
// Fast sigmoid: MUFU.EX2-based exp + MUFU.RCP division (~4 SASS ops).
__device__ __forceinline__ float sigm(float v) {
    return __fdividef(1.0f, 1.0f + __expf(-v));
}

// ---------------- RMS split norm -> bf16 ----------------
__global__ void rmsnorm_kernel(const float* __restrict__ x,
                               const float* __restrict__ ls,
                               const float* __restrict__ rs,
                               const float* __restrict__ ss,
                               __nv_bfloat16* __restrict__ xn) {
    __shared__ float wsum[8];
    int row = blockIdx.x;
    int tid = threadIdx.x;                 // 256 threads, 4 elems each
    const float* xr = x + (size_t)row * DIMS;
    float4 xv = ((const float4*)xr)[tid];
    float s = xv.x*xv.x + xv.y*xv.y + xv.z*xv.z + xv.w*xv.w;
    #pragma unroll
    for (int o = 16; o; o >>= 1) s += __shfl_xor_sync(0xffffffffu, s, o);
    if ((tid & 31) == 0) wsum[tid >> 5] = s;
    __syncthreads();
    int half = tid >> 7;
    float tot = wsum[half*4+0] + wsum[half*4+1] + wsum[half*4+2] + wsum[half*4+3];
    float n = sqrtf(tot) * 0.04419417382415922f + 1e-8f;   // 1/sqrt(512)
    float inv = 1.0f / n;
    const float* sc = half ? rs : ls;
    int jb = (tid*4) & 511;
    float4 scv = ((const float4*)sc)[jb >> 2];
    float4 ssv = ((const float4*)ss)[tid];
    __nv_bfloat162 p0 = __floats2bfloat162_rn(xv.x * scv.x * inv * ssv.x,
                                              xv.y * scv.y * inv * ssv.y);
    __nv_bfloat162 p1 = __floats2bfloat162_rn(xv.z * scv.z * inv * ssv.z,
                                              xv.w * scv.w * inv * ssv.w);
    __nv_bfloat162* dst = (__nv_bfloat162*)(xn + (size_t)row * DIMS);
    dst[tid*2]   = p0;
    dst[tid*2+1] = p1;
}

// ---------------- Weight prep: u/gin interleave at 8-column granularity ----------------
// z=0: Wk col c         -> WT row c                              (d-plane logits)
// z=1: Wugg col c (u)   -> WT row 2048 + 16*(c>>3) + (c&7)       (u block)
// z=2: Wugg col 2048+c  -> WT row 2048 + 16*(c>>3) + 8 + (c&7)   (gin block)
// z=3: Wugg col 4096+c  -> WT row 6144 + c                       (gout)
__global__ void prep_WT(const float* __restrict__ Wk, const float* __restrict__ Wugg,
                        __nv_bfloat16* __restrict__ dst) {
    __shared__ float tile[32][33];
    int z = blockIdx.z;
    const float* src = (z == 0) ? Wk : (Wugg + (z - 1) * 2048);
    int srcLD = (z == 0) ? 2048 : 6144;
    int r0 = blockIdx.y * 32, c0 = blockIdx.x * 32;
    int tx = threadIdx.x, ty = threadIdx.y;   // 32 x 8
    #pragma unroll
    for (int i = 0; i < 32; i += 8)
        tile[ty+i][tx] = src[(size_t)(r0+ty+i)*srcLD + c0 + tx];
    __syncthreads();
    #pragma unroll
    for (int i = 0; i < 32; i += 8) {
        int c = c0 + ty + i;
        int dstRow;
        if      (z == 0) dstRow = c;
        else if (z == 1) dstRow = 2048 + 16*(c >> 3) + (c & 7);
        else if (z == 2) dstRow = 2048 + 16*(c >> 3) + 8 + (c & 7);
        else             dstRow = 6144 + c;
        dst[(size_t)dstRow*1024 + r0 + tx] = __float2bfloat16_rn(tile[tx][ty+i]);
    }
}

// ---------------- Plain transpose fp32 -> bf16 (Wout) ----------------
__global__ void transpose_bf16(const float* __restrict__ src, __nv_bfloat16* __restrict__ dst,
                               int R, int C) {
    __shared__ float tile[32][33];
    int r0 = blockIdx.y * 32, c0 = blockIdx.x * 32;
    int tx = threadIdx.x, ty = threadIdx.y;   // 32 x 8
    #pragma unroll
    for (int i = 0; i < 32; i += 8)
        tile[ty+i][tx] = src[(size_t)(r0+ty+i)*C + c0 + tx];
    __syncthreads();
    #pragma unroll
    for (int i = 0; i < 32; i += 8)
        dst[(size_t)(c0+ty+i)*R + r0 + tx] = __float2bfloat16_rn(tile[tx][ty+i]);
}

// ---------------- Legacy-MMA bf16 GEMM: CTA 128x128, 4 warps of 64x64, 2 CTA/SM ----------------
// R14 structure, but smem rows PADDED to 144B (9x16B) instead of XOR-swizzled:
// 16B-chunk bank = (9r + c) mod 8 = (r+c) mod 8 -> ldmatrix phases conflict-free,
// and the per-kk offset becomes a compile-time LDSM immediate (kills LOP3+IADD per LDSM).
#define BK 64
#define NST 3
#define LDP 144                // padded row pitch in bytes
#define AST (128*LDP)          // 18432 bytes per A stage
#define BST (128*LDP)          // 18432 bytes per B stage
#define GEMM_SMEM (NST*(AST+BST))   // 110592 B per CTA (2 CTA/SM = 216KB <= 228KB)

__global__ void __launch_bounds__(128, 2)
gemm_bf16(const __nv_bfloat16* __restrict__ A, const __nv_bfloat16* __restrict__ B,
          int N, int K, int NIT, int mode,
          __nv_bfloat16* __restrict__ pD, __nv_bfloat16* __restrict__ pU2,
          __nv_bfloat16* __restrict__ pGO,
          float* __restrict__ Cout, const float* __restrict__ resid) {
    extern __shared__ char smraw[];
    const uint32_t sbase = smem_u32(smraw);

    const int tid  = threadIdx.x;          // 0..127
    const int wid  = tid >> 5;             // 0..3
    const int lane = tid & 31;
    const int m0 = blockIdx.y * 128;
    const int n0 = blockIdx.x * 128;
    const int wm0 = (wid >> 1) * 64;       // warp row origin (0/64)
    const int wn0 = (wid & 1) * 64;        // warp col origin (0/64)
    const int blk = lane >> 3;             // 0..3
    const int lr8 = lane & 7;
    const int kb2 = (blk >> 1) * 16;       // +16B for k8..15 half

    // Hoisted fill addressing: 128 threads cover 16 rows/sweep, 8 sweeps per tile
    uint32_t sOff[8];
    uint32_t goA[8], goB[8];
    {
        int r = tid >> 3, c = tid & 7;
        #pragma unroll
        for (int i = 0; i < 8; i++) {
            int rr = r + i * 16;
            sOff[i] = (uint32_t)(rr * LDP + c * 16);
            goA[i] = (uint32_t)((m0 + rr) * K + c * 8);
            goB[i] = (uint32_t)((n0 + rr) * K + c * 8);
        }
    }

    // Per-warp ldmatrix row offsets (padded linear; kk offset folds into immediate)
    uint32_t offA[4], offB[4];
    #pragma unroll
    for (int mt = 0; mt < 4; mt++) {
        int r = wm0 + mt*16 + (blk & 1)*8 + lr8;
        offA[mt] = (uint32_t)(r * LDP) + kb2;
    }
    #pragma unroll
    for (int np = 0; np < 4; np++) {
        int r = wn0 + np*16 + (blk & 1)*8 + lr8;
        offB[np] = (uint32_t)(r * LDP) + kb2;
    }

    float c[4][8][4];
    #pragma unroll
    for (int i = 0; i < 4; i++)
        #pragma unroll
        for (int j = 0; j < 8; j++)
            #pragma unroll
            for (int e = 0; e < 4; e++) c[i][j][e] = 0.0f;

    // Prologue: fill all 3 stages
    #pragma unroll
    for (int pf = 0; pf < NST; ++pf) {
        const uint32_t aS = sbase + pf*(AST+BST);
        const uint32_t bS = aS + AST;
        const uint32_t k0 = pf * BK;
        #pragma unroll
        for (int i = 0; i < 8; i++) cp16(aS + sOff[i], A + goA[i] + k0);
        #pragma unroll
        for (int i = 0; i < 8; i++) cp16(bS + sOff[i], B + goB[i] + k0);
        CP_COMMIT();
    }

    for (int it = 0; it < NIT; ++it) {
        const int s = it % NST;
        const uint32_t aS = sbase + s*(AST+BST);
        const uint32_t bS = aS + AST;

        int rem = NIT - 1 - it;
        if (rem >= 2)      asm volatile("cp.async.wait_group 2;" ::: "memory");
        else if (rem == 1) asm volatile("cp.async.wait_group 1;" ::: "memory");
        else               asm volatile("cp.async.wait_group 0;" ::: "memory");
        __syncthreads();

        #pragma unroll
        for (int kk = 0; kk < 4; ++kk) {
            uint32_t a[4][4], b[4][4];
            #pragma unroll
            for (int mt = 0; mt < 4; mt++)
                ldm_x4(a[mt], aS + offA[mt] + kk*32);   // kk*32 folds into immediate
            #pragma unroll
            for (int np = 0; np < 4; np++)
                ldm_x4(b[np], bS + offB[np] + kk*32);
            #pragma unroll
            for (int mt = 0; mt < 4; mt++)
                #pragma unroll
                for (int nt = 0; nt < 8; nt++) {
                    int np = nt >> 1, odd = nt & 1;
                    mma_bf16(c[mt][nt], a[mt], b[np][odd], b[np][2 + odd]);
                }
        }
        __syncthreads();   // everyone done reading stage s

        if (it + 3 < NIT) {
            const uint32_t k0 = (it + 3) * BK;
            #pragma unroll
            for (int i = 0; i < 8; i++) cp16(aS + sOff[i], A + goA[i] + k0);
            #pragma unroll
            for (int i = 0; i < 8; i++) cp16(bS + sOff[i], B + goB[i] + k0);
            CP_COMMIT();
        }
    }

    // Epilogue (R14, frozen)
    const int g = lane >> 2, tig = lane & 3;
    if (mode == 0) {
        if (n0 < 2048) {
            #pragma unroll
            for (int mt = 0; mt < 4; mt++) {
                int row = m0 + wm0 + mt*16 + g;
                #pragma unroll
                for (int nt = 0; nt < 8; nt++) {
                    int st = n0 + wn0 + nt*8 + 2*tig;
                    float d0 = sigm(-c[mt][nt][0]), d1 = sigm(-c[mt][nt][1]);
                    float d2 = sigm(-c[mt][nt][2]), d3 = sigm(-c[mt][nt][3]);
                    *(__nv_bfloat162*)(pD + (size_t)row * STATE + st)
                        = __floats2bfloat162_rn(d0, d1);
                    *(__nv_bfloat162*)(pD + (size_t)(row+8) * STATE + st)
                        = __floats2bfloat162_rn(d2, d3);
                }
            }
        } else if (n0 < 6144) {
            const int sbase0 = ((n0 - 2048) + wn0) >> 1;
            #pragma unroll
            for (int mt = 0; mt < 4; mt++) {
                int row = m0 + wm0 + mt*16 + g;
                #pragma unroll
                for (int j = 0; j < 4; j++) {
                    const int nte = 2*j, nto = 2*j + 1;
                    int st = sbase0 + j*8 + 2*tig;
                    float u20 = c[mt][nte][0] * sigm(c[mt][nto][0]);
                    float u21 = c[mt][nte][1] * sigm(c[mt][nto][1]);
                    float u22 = c[mt][nte][2] * sigm(c[mt][nto][2]);
                    float u23 = c[mt][nte][3] * sigm(c[mt][nto][3]);
                    *(__nv_bfloat162*)(pU2 + (size_t)row * STATE + st)
                        = __floats2bfloat162_rn(u20, u21);
                    *(__nv_bfloat162*)(pU2 + (size_t)(row+8) * STATE + st)
                        = __floats2bfloat162_rn(u22, u23);
                }
            }
        } else {
            #pragma unroll
            for (int mt = 0; mt < 4; mt++) {
                int row = m0 + wm0 + mt*16 + g;
                #pragma unroll
                for (int nt = 0; nt < 8; nt++) {
                    int st = (n0 - 6144) + wn0 + nt*8 + 2*tig;
                    float v0 = sigm(c[mt][nt][0]), v1 = sigm(c[mt][nt][1]);
                    float v2 = sigm(c[mt][nt][2]), v3 = sigm(c[mt][nt][3]);
                    *(__nv_bfloat162*)(pGO + (size_t)row * STATE + st)
                        = __floats2bfloat162_rn(v0, v1);
                    *(__nv_bfloat162*)(pGO + (size_t)(row+8) * STATE + st)
                        = __floats2bfloat162_rn(v2, v3);
                }
            }
        }
    } else {
        #pragma unroll
        for (int mt = 0; mt < 4; mt++) {
            int row = m0 + wm0 + mt*16 + g;
            #pragma unroll
            for (int nt = 0; nt < 8; nt++) {
                int col = n0 + wn0 + nt*8 + 2*tig;
                float v0 = c[mt][nt][0] + resid[(size_t)row * N + col];
                float v1 = c[mt][nt][1] + resid[(size_t)row * N + col + 1];
                float v2 = c[mt][nt][2] + resid[(size_t)(row+8) * N + col];
                float v3 = c[mt][nt][3] + resid[(size_t)(row+8) * N + col + 1];
                *(float2*)(Cout + (size_t)row * N + col)     = make_float2(v0, v1);
                *(float2*)(Cout + (size_t)(row+8) * N + col) = make_float2(v2, v3);
            }
        }
    }
}

// ---------------- Chunked linear-recurrence scan (d, u2, gout all bf16) ----------------
__global__ void scan_phase1(const __nv_bfloat16* __restrict__ CD,
                            const __nv_bfloat16* __restrict__ CU2,
                            float* __restrict__ chA, float* __restrict__ chB) {
    int cidx  = blockIdx.x * blockDim.x + threadIdx.x;   // 0..2047
    int chunk = blockIdx.y;
    int b     = blockIdx.z;
    float Aacc = 1.0f, Bacc = 0.0f;
    int t0 = chunk * TCH;
    size_t row0 = (size_t)b * SEQ + t0;
    float dprev = (t0 == 0) ? 0.0f : __bfloat162float(CD[(row0 - 1) * STATE + cidx]);
    for (int tl = 0; tl < TCH; tl++) {
        size_t r = (row0 + tl) * STATE + cidx;
        float d  = __bfloat162float(CD[r]);
        float u2 = __bfloat162float(CU2[r]);
        float a  = 1.0f - dprev;
        dprev = d;
        float up = u2 * d;
        Aacc = a * Aacc;
        Bacc = a * Bacc + up;
    }
    int idx = (b * NCH + chunk) * STATE + cidx;
    chA[idx] = Aacc;
    chB[idx] = Bacc;
}

__global__ void scan_phase2(const float* __restrict__ chA,
                            const float* __restrict__ chB,
                            float* __restrict__ hin) {
    int i = blockIdx.x * blockDim.x + threadIdx.x;   // b*2048+c
    int b = i >> 11, cidx = i & 2047;
    float h = 0.0f;
    for (int ch = 0; ch < NCH; ch++) {
        int idx = (b * NCH + ch) * STATE + cidx;
        hin[idx] = h;
        h = chA[idx] * h + chB[idx];
    }
}

__global__ void scan_phase3(const __nv_bfloat16* __restrict__ CD,
                            const __nv_bfloat16* __restrict__ CU2,
                            const __nv_bfloat16* __restrict__ CGO,
                            const float* __restrict__ hin,
                            __nv_bfloat16* __restrict__ out1) {
    int cidx  = blockIdx.x * blockDim.x + threadIdx.x;
    int chunk = blockIdx.y;
    int b     = blockIdx.z;
    float h = hin[(b * NCH + chunk) * STATE + cidx];
    int t0 = chunk * TCH;
    size_t row0 = (size_t)b * SEQ + t0;
    float dprev = (t0 == 0) ? 0.0f : __bfloat162float(CD[(row0 - 1) * STATE + cidx]);
    for (int tl = 0; tl < TCH; tl++) {
        size_t r = (row0 + tl) * STATE + cidx;
        float d  = __bfloat162float(CD[r]);
        float u2 = __bfloat162float(CU2[r]);
        float go = __bfloat162float(CGO[r]);
        float a  = 1.0f - dprev;
        dprev = d;
        h = a * h + u2 * d;
        out1[r] = __float2bfloat16_rn(h * go);
    }
}

// ---------------- Launch ----------------
extern "C" void kernel_launch(void* const* d_in, const int* in_sizes, int n_in,
                              void* d_out, int out_size) {
    const float* x    = (const float*)d_in[0];
    const float* ls   = (const float*)d_in[1];
    const float* rs   = (const float*)d_in[2];
    const float* ss   = (const float*)d_in[3];
    const float* Wk   = (const float*)d_in[4];
    const float* Wugg = (const float*)d_in[5];
    const float* Wout = (const float*)d_in[6];
    float* y = (float*)d_out;

    __nv_bfloat16 *p_xn, *p_WT, *p_WoutT, *p_out1, *p_CD, *p_CU2, *p_CGO;
    float *p_chA, *p_chB, *p_hin;
    cudaGetSymbolAddress((void**)&p_xn,    g_xn);
    cudaGetSymbolAddress((void**)&p_WT,    g_WT);
    cudaGetSymbolAddress((void**)&p_WoutT, g_WoutT);
    cudaGetSymbolAddress((void**)&p_CD,    g_CD);
    cudaGetSymbolAddress((void**)&p_CU2,   g_CU2);
    cudaGetSymbolAddress((void**)&p_CGO,   g_CGO);
    cudaGetSymbolAddress((void**)&p_out1,  g_out1);
    cudaGetSymbolAddress((void**)&p_chA,   g_chA);
    cudaGetSymbolAddress((void**)&p_chB,   g_chB);
    cudaGetSymbolAddress((void**)&p_hin,   g_hin);

    cudaFuncSetAttribute(gemm_bf16, cudaFuncAttributeMaxDynamicSharedMemorySize, GEMM_SMEM);

    dim3 blk(32, 8);

    rmsnorm_kernel<<<ROWS, 256>>>(x, ls, rs, ss, p_xn);
    prep_WT<<<dim3(2048/32, 1024/32, 4), blk>>>(Wk, Wugg, p_WT);
    transpose_bf16<<<dim3(1024/32, 2048/32), blk>>>(Wout, p_WoutT, 2048, 1024);
    // global launch index 5 -> ncu profiles GEMM1
    gemm_bf16<<<dim3(NTOT/128, ROWS/128), 128, GEMM_SMEM>>>(
        p_xn, p_WT, NTOT, DIMS, DIMS/BK, 0,
        p_CD, p_CU2, p_CGO, nullptr, nullptr);

    scan_phase1<<<dim3(STATE/256, NCH, BATCH), 256>>>(p_CD, p_CU2, p_chA, p_chB);
    scan_phase2<<<(BATCH*STATE)/256, 256>>>(p_chA, p_chB, p_hin);
    scan_phase3<<<dim3(STATE/256, NCH, BATCH), 256>>>(p_CD, p_CU2, p_CGO, p_hin, p_out1);

    gemm_bf16<<<dim3(DIMS/128, ROWS/128), 128, GEMM_SMEM>>>(
        p_out1, p_WoutT, DIMS, STATE, STATE/BK, 1,
        nullptr, nullptr, nullptr, y, x);
}

// round 16
// speedup vs baseline: 1.1728x; 1.1728x over previous
#include <cuda_runtime.h>
#include <cuda_bf16.h>
#include <math.h>
#include <stdint.h>

// ---------------- Problem constants ----------------
#define BATCH   4
#define SEQ     2048
#define ROWS    (BATCH*SEQ)      // 8192
#define DIMS    1024
#define STATE   2048             // 2*DIMS
#define NTOT    (4*STATE)        // 8192 logical GEMM1 columns [K | u/gin 8-blocked | gout]
#define TCH     128              // scan chunk length
#define NCH     (SEQ/TCH)        // 16 chunks

// ---------------- Scratch (device globals; no allocation allowed) ----------------
__device__ __nv_bfloat16 g_xn[(size_t)ROWS*DIMS];       // 16MB  normalized input (bf16)
__device__ __nv_bfloat16 g_WT[(size_t)NTOT*DIMS];       // 16MB  packed weights^T bf16
__device__ __nv_bfloat16 g_WoutT[(size_t)DIMS*STATE];   // 4MB   Wout^T as [n,k] bf16
__device__ __nv_bfloat16 g_CD [(size_t)ROWS*STATE];     // 32MB  d = 1-sig(K) bf16
__device__ __nv_bfloat16 g_CU2[(size_t)ROWS*STATE];     // 32MB  u2 = u*sig(gin) bf16
__device__ __nv_bfloat16 g_CGO[(size_t)ROWS*STATE];     // 32MB  sig(gout) bf16
__device__ __nv_bfloat16 g_out1[(size_t)ROWS*STATE];    // 32MB  h*sig(gout) bf16
__device__ float g_chA[BATCH*NCH*STATE];
__device__ float g_chB[BATCH*NCH*STATE];
__device__ float g_hin[BATCH*NCH*STATE];

// ---------------- Helpers ----------------
__device__ __forceinline__ uint32_t smem_u32(const void* p) {
    uint32_t a;
    asm("{ .reg .u64 t; cvta.to.shared.u64 t, %1; cvt.u32.u64 %0, t; }" : "=r"(a) : "l"(p));
    return a;
}
__device__ __forceinline__ void cp16(uint32_t dst, const void* src) {
    asm volatile("cp.async.cg.shared.global [%0], [%1], 16;" :: "r"(dst), "l"(src) : "memory");
}
#define CP_COMMIT() asm volatile("cp.async.commit_group;" ::: "memory")

__device__ __forceinline__ void ldm_x4(uint32_t* r, uint32_t addr) {
    asm volatile("ldmatrix.sync.aligned.m8n8.x4.shared.b16 {%0,%1,%2,%3}, [%4];"
                 : "=r"(r[0]), "=r"(r[1]), "=r"(r[2]), "=r"(r[3]) : "r"(addr));
}
__device__ __forceinline__ void mma_bf16(float* c, const uint32_t* a,
                                         uint32_t b0, uint32_t b1) {
    asm volatile(
        "mma.sync.aligned.m16n8k16.row.col.f32.bf16.bf16.f32 "
        "{%0,%1,%2,%3},{%4,%5,%6,%7},{%8,%9},{%0,%1,%2,%3};"
        : "+f"(c[0]), "+f"(c[1]), "+f"(c[2]), "+f"(c[3])
        : "r"(a[0]), "r"(a[1]), "r"(a[2]), "r"(a[3]), "r"(b0), "r"(b1));
}
// Fast sigmoid: MUFU.EX2-based exp + MUFU.RCP division (~4 SASS ops).
__device__ __forceinline__ float sigm(float v) {
    return __fdividef(1.0f, 1.0f + __expf(-v));
}

// ---------------- RMS split norm -> bf16 ----------------
__global__ void rmsnorm_kernel(const float* __restrict__ x,
                               const float* __restrict__ ls,
                               const float* __restrict__ rs,
                               const float* __restrict__ ss,
                               __nv_bfloat16* __restrict__ xn) {
    __shared__ float wsum[8];
    int row = blockIdx.x;
    int tid = threadIdx.x;                 // 256 threads, 4 elems each
    const float* xr = x + (size_t)row * DIMS;
    float4 xv = ((const float4*)xr)[tid];
    float s = xv.x*xv.x + xv.y*xv.y + xv.z*xv.z + xv.w*xv.w;
    #pragma unroll
    for (int o = 16; o; o >>= 1) s += __shfl_xor_sync(0xffffffffu, s, o);
    if ((tid & 31) == 0) wsum[tid >> 5] = s;
    __syncthreads();
    int half = tid >> 7;
    float tot = wsum[half*4+0] + wsum[half*4+1] + wsum[half*4+2] + wsum[half*4+3];
    float n = sqrtf(tot) * 0.04419417382415922f + 1e-8f;   // 1/sqrt(512)
    float inv = 1.0f / n;
    const float* sc = half ? rs : ls;
    int jb = (tid*4) & 511;
    float4 scv = ((const float4*)sc)[jb >> 2];
    float4 ssv = ((const float4*)ss)[tid];
    __nv_bfloat162 p0 = __floats2bfloat162_rn(xv.x * scv.x * inv * ssv.x,
                                              xv.y * scv.y * inv * ssv.y);
    __nv_bfloat162 p1 = __floats2bfloat162_rn(xv.z * scv.z * inv * ssv.z,
                                              xv.w * scv.w * inv * ssv.w);
    __nv_bfloat162* dst = (__nv_bfloat162*)(xn + (size_t)row * DIMS);
    dst[tid*2]   = p0;
    dst[tid*2+1] = p1;
}

// ---------------- Weight prep: u/gin interleave at 8-column granularity ----------------
// z=0: Wk col c         -> WT row c                              (d-plane logits)
// z=1: Wugg col c (u)   -> WT row 2048 + 16*(c>>3) + (c&7)       (u block)
// z=2: Wugg col 2048+c  -> WT row 2048 + 16*(c>>3) + 8 + (c&7)   (gin block)
// z=3: Wugg col 4096+c  -> WT row 6144 + c                       (gout)
__global__ void prep_WT(const float* __restrict__ Wk, const float* __restrict__ Wugg,
                        __nv_bfloat16* __restrict__ dst) {
    __shared__ float tile[32][33];
    int z = blockIdx.z;
    const float* src = (z == 0) ? Wk : (Wugg + (z - 1) * 2048);
    int srcLD = (z == 0) ? 2048 : 6144;
    int r0 = blockIdx.y * 32, c0 = blockIdx.x * 32;
    int tx = threadIdx.x, ty = threadIdx.y;   // 32 x 8
    #pragma unroll
    for (int i = 0; i < 32; i += 8)
        tile[ty+i][tx] = src[(size_t)(r0+ty+i)*srcLD + c0 + tx];
    __syncthreads();
    #pragma unroll
    for (int i = 0; i < 32; i += 8) {
        int c = c0 + ty + i;
        int dstRow;
        if      (z == 0) dstRow = c;
        else if (z == 1) dstRow = 2048 + 16*(c >> 3) + (c & 7);
        else if (z == 2) dstRow = 2048 + 16*(c >> 3) + 8 + (c & 7);
        else             dstRow = 6144 + c;
        dst[(size_t)dstRow*1024 + r0 + tx] = __float2bfloat16_rn(tile[tx][ty+i]);
    }
}

// ---------------- Plain transpose fp32 -> bf16 (Wout) ----------------
__global__ void transpose_bf16(const float* __restrict__ src, __nv_bfloat16* __restrict__ dst,
                               int R, int C) {
    __shared__ float tile[32][33];
    int r0 = blockIdx.y * 32, c0 = blockIdx.x * 32;
    int tx = threadIdx.x, ty = threadIdx.y;   // 32 x 8
    #pragma unroll
    for (int i = 0; i < 32; i += 8)
        tile[ty+i][tx] = src[(size_t)(r0+ty+i)*C + c0 + tx];
    __syncthreads();
    #pragma unroll
    for (int i = 0; i < 32; i += 8)
        dst[(size_t)(c0+ty+i)*R + r0 + tx] = __float2bfloat16_rn(tile[tx][ty+i]);
}

// ---------------- Legacy-MMA bf16 GEMM: CTA 128x128, 4 warps of 64x64, 2 CTA/SM ----------------
// R14 version, measured fast — FROZEN (XOR swizzle, 128B rows).
#define BK 64
#define NST 3
#define AST (128*BK*2)         // 16384 bytes per A stage
#define BST (128*BK*2)         // 16384 bytes per B stage
#define GEMM_SMEM (NST*(AST+BST))   // 98304 = 96KB

__global__ void __launch_bounds__(128, 2)
gemm_bf16(const __nv_bfloat16* __restrict__ A, const __nv_bfloat16* __restrict__ B,
          int N, int K, int NIT, int mode,
          __nv_bfloat16* __restrict__ pD, __nv_bfloat16* __restrict__ pU2,
          __nv_bfloat16* __restrict__ pGO,
          float* __restrict__ Cout, const float* __restrict__ resid) {
    extern __shared__ char smraw[];
    const uint32_t sbase = smem_u32(smraw);

    const int tid  = threadIdx.x;          // 0..127
    const int wid  = tid >> 5;             // 0..3
    const int lane = tid & 31;
    const int m0 = blockIdx.y * 128;
    const int n0 = blockIdx.x * 128;
    const int wm0 = (wid >> 1) * 64;       // warp row origin (0/64)
    const int wn0 = (wid & 1) * 64;        // warp col origin (0/64)
    const int blk = lane >> 3;             // 0..3
    const int lr8 = lane & 7;
    const int kb2 = (blk >> 1) * 16;       // +16B for k8..15 half

    // Hoisted fill addressing: 128 threads cover 16 rows/sweep, 8 sweeps per tile
    uint32_t sOff[8];
    uint32_t goA[8], goB[8];
    {
        int r = tid >> 3, c = tid & 7;
        #pragma unroll
        for (int i = 0; i < 8; i++) {
            int rr = r + i * 16;
            sOff[i] = (uint32_t)(rr * 128 + ((c ^ (rr & 7)) << 4));
            goA[i] = (uint32_t)((m0 + rr) * K + c * 8);
            goB[i] = (uint32_t)((n0 + rr) * K + c * 8);
        }
    }

    uint32_t offA[4], xrA[4], offB[4], xrB[4];
    #pragma unroll
    for (int mt = 0; mt < 4; mt++) {
        int r = wm0 + mt*16 + (blk & 1)*8 + lr8;
        offA[mt] = (uint32_t)r * 128u;
        xrA[mt]  = (uint32_t)(r & 7) << 4;
    }
    #pragma unroll
    for (int np = 0; np < 4; np++) {
        int r = wn0 + np*16 + (blk & 1)*8 + lr8;
        offB[np] = (uint32_t)r * 128u;
        xrB[np]  = (uint32_t)(r & 7) << 4;
    }

    float c[4][8][4];
    #pragma unroll
    for (int i = 0; i < 4; i++)
        #pragma unroll
        for (int j = 0; j < 8; j++)
            #pragma unroll
            for (int e = 0; e < 4; e++) c[i][j][e] = 0.0f;

    // Prologue: fill all 3 stages
    #pragma unroll
    for (int pf = 0; pf < NST; ++pf) {
        const uint32_t aS = sbase + pf*(AST+BST);
        const uint32_t bS = aS + AST;
        const uint32_t k0 = pf * BK;
        #pragma unroll
        for (int i = 0; i < 8; i++) cp16(aS + sOff[i], A + goA[i] + k0);
        #pragma unroll
        for (int i = 0; i < 8; i++) cp16(bS + sOff[i], B + goB[i] + k0);
        CP_COMMIT();
    }

    for (int it = 0; it < NIT; ++it) {
        const int s = it % NST;
        const uint32_t aS = sbase + s*(AST+BST);
        const uint32_t bS = aS + AST;

        int rem = NIT - 1 - it;
        if (rem >= 2)      asm volatile("cp.async.wait_group 2;" ::: "memory");
        else if (rem == 1) asm volatile("cp.async.wait_group 1;" ::: "memory");
        else               asm volatile("cp.async.wait_group 0;" ::: "memory");
        __syncthreads();

        #pragma unroll
        for (int kk = 0; kk < 4; ++kk) {
            uint32_t a[4][4], b[4][4];
            const uint32_t kbase = (uint32_t)(kk*32) + kb2;
            #pragma unroll
            for (int mt = 0; mt < 4; mt++)
                ldm_x4(a[mt], aS + offA[mt] + (kbase ^ xrA[mt]));
            #pragma unroll
            for (int np = 0; np < 4; np++)
                ldm_x4(b[np], bS + offB[np] + (kbase ^ xrB[np]));
            #pragma unroll
            for (int mt = 0; mt < 4; mt++)
                #pragma unroll
                for (int nt = 0; nt < 8; nt++) {
                    int np = nt >> 1, odd = nt & 1;
                    mma_bf16(c[mt][nt], a[mt], b[np][odd], b[np][2 + odd]);
                }
        }
        __syncthreads();   // everyone done reading stage s

        if (it + 3 < NIT) {
            const uint32_t k0 = (it + 3) * BK;
            #pragma unroll
            for (int i = 0; i < 8; i++) cp16(aS + sOff[i], A + goA[i] + k0);
            #pragma unroll
            for (int i = 0; i < 8; i++) cp16(bS + sOff[i], B + goB[i] + k0);
            CP_COMMIT();
        }
    }

    // Epilogue (R14, frozen)
    const int g = lane >> 2, tig = lane & 3;
    if (mode == 0) {
        if (n0 < 2048) {
            #pragma unroll
            for (int mt = 0; mt < 4; mt++) {
                int row = m0 + wm0 + mt*16 + g;
                #pragma unroll
                for (int nt = 0; nt < 8; nt++) {
                    int st = n0 + wn0 + nt*8 + 2*tig;
                    float d0 = sigm(-c[mt][nt][0]), d1 = sigm(-c[mt][nt][1]);
                    float d2 = sigm(-c[mt][nt][2]), d3 = sigm(-c[mt][nt][3]);
                    *(__nv_bfloat162*)(pD + (size_t)row * STATE + st)
                        = __floats2bfloat162_rn(d0, d1);
                    *(__nv_bfloat162*)(pD + (size_t)(row+8) * STATE + st)
                        = __floats2bfloat162_rn(d2, d3);
                }
            }
        } else if (n0 < 6144) {
            const int sbase0 = ((n0 - 2048) + wn0) >> 1;
            #pragma unroll
            for (int mt = 0; mt < 4; mt++) {
                int row = m0 + wm0 + mt*16 + g;
                #pragma unroll
                for (int j = 0; j < 4; j++) {
                    const int nte = 2*j, nto = 2*j + 1;
                    int st = sbase0 + j*8 + 2*tig;
                    float u20 = c[mt][nte][0] * sigm(c[mt][nto][0]);
                    float u21 = c[mt][nte][1] * sigm(c[mt][nto][1]);
                    float u22 = c[mt][nte][2] * sigm(c[mt][nto][2]);
                    float u23 = c[mt][nte][3] * sigm(c[mt][nto][3]);
                    *(__nv_bfloat162*)(pU2 + (size_t)row * STATE + st)
                        = __floats2bfloat162_rn(u20, u21);
                    *(__nv_bfloat162*)(pU2 + (size_t)(row+8) * STATE + st)
                        = __floats2bfloat162_rn(u22, u23);
                }
            }
        } else {
            #pragma unroll
            for (int mt = 0; mt < 4; mt++) {
                int row = m0 + wm0 + mt*16 + g;
                #pragma unroll
                for (int nt = 0; nt < 8; nt++) {
                    int st = (n0 - 6144) + wn0 + nt*8 + 2*tig;
                    float v0 = sigm(c[mt][nt][0]), v1 = sigm(c[mt][nt][1]);
                    float v2 = sigm(c[mt][nt][2]), v3 = sigm(c[mt][nt][3]);
                    *(__nv_bfloat162*)(pGO + (size_t)row * STATE + st)
                        = __floats2bfloat162_rn(v0, v1);
                    *(__nv_bfloat162*)(pGO + (size_t)(row+8) * STATE + st)
                        = __floats2bfloat162_rn(v2, v3);
                }
            }
        }
    } else {
        #pragma unroll
        for (int mt = 0; mt < 4; mt++) {
            int row = m0 + wm0 + mt*16 + g;
            #pragma unroll
            for (int nt = 0; nt < 8; nt++) {
                int col = n0 + wn0 + nt*8 + 2*tig;
                float v0 = c[mt][nt][0] + resid[(size_t)row * N + col];
                float v1 = c[mt][nt][1] + resid[(size_t)row * N + col + 1];
                float v2 = c[mt][nt][2] + resid[(size_t)(row+8) * N + col];
                float v3 = c[mt][nt][3] + resid[(size_t)(row+8) * N + col + 1];
                *(float2*)(Cout + (size_t)row * N + col)     = make_float2(v0, v1);
                *(float2*)(Cout + (size_t)(row+8) * N + col) = make_float2(v2, v3);
            }
        }
    }
}

// ---------------- Vectorized scan (2 channels/thread, bf16x2 / float2 traffic) ----------------
// a_t = 1 - d_{t-1}; u'_t = u2_t * d_t; h_t = a_t h_{t-1} + u'_t  (per channel)
__global__ void scan_phase1(const __nv_bfloat16* __restrict__ CD,
                            const __nv_bfloat16* __restrict__ CU2,
                            float* __restrict__ chA, float* __restrict__ chB) {
    int cidx  = (blockIdx.x * blockDim.x + threadIdx.x) * 2;   // 0,2,..2046
    int chunk = blockIdx.y;
    int b     = blockIdx.z;
    float A0 = 1.0f, B0 = 0.0f, A1 = 1.0f, B1 = 0.0f;
    int t0 = chunk * TCH;
    size_t row0 = (size_t)b * SEQ + t0;
    float dp0 = 0.0f, dp1 = 0.0f;
    if (t0 != 0) {
        __nv_bfloat162 dv = *(const __nv_bfloat162*)(CD + (row0 - 1) * STATE + cidx);
        dp0 = __bfloat162float(dv.x); dp1 = __bfloat162float(dv.y);
    }
    for (int tl = 0; tl < TCH; tl++) {
        size_t r = (row0 + tl) * STATE + cidx;
        __nv_bfloat162 dv = *(const __nv_bfloat162*)(CD + r);
        __nv_bfloat162 uv = *(const __nv_bfloat162*)(CU2 + r);
        float d0 = __bfloat162float(dv.x), d1 = __bfloat162float(dv.y);
        float u0 = __bfloat162float(uv.x), u1 = __bfloat162float(uv.y);
        float a0 = 1.0f - dp0, a1 = 1.0f - dp1;
        dp0 = d0; dp1 = d1;
        A0 = a0 * A0;  B0 = a0 * B0 + u0 * d0;
        A1 = a1 * A1;  B1 = a1 * B1 + u1 * d1;
    }
    int idx = (b * NCH + chunk) * STATE + cidx;
    *(float2*)(chA + idx) = make_float2(A0, A1);
    *(float2*)(chB + idx) = make_float2(B0, B1);
}

__global__ void scan_phase2(const float* __restrict__ chA,
                            const float* __restrict__ chB,
                            float* __restrict__ hin) {
    int i = (blockIdx.x * blockDim.x + threadIdx.x) * 2;   // pair index into b*2048+c
    int b = i >> 11, cidx = i & 2047;
    float h0 = 0.0f, h1 = 0.0f;
    for (int ch = 0; ch < NCH; ch++) {
        int idx = (b * NCH + ch) * STATE + cidx;
        *(float2*)(hin + idx) = make_float2(h0, h1);
        float2 av = *(const float2*)(chA + idx);
        float2 bv = *(const float2*)(chB + idx);
        h0 = av.x * h0 + bv.x;
        h1 = av.y * h1 + bv.y;
    }
}

__global__ void scan_phase3(const __nv_bfloat16* __restrict__ CD,
                            const __nv_bfloat16* __restrict__ CU2,
                            const __nv_bfloat16* __restrict__ CGO,
                            const float* __restrict__ hin,
                            __nv_bfloat16* __restrict__ out1) {
    int cidx  = (blockIdx.x * blockDim.x + threadIdx.x) * 2;
    int chunk = blockIdx.y;
    int b     = blockIdx.z;
    float2 hv = *(const float2*)(hin + (b * NCH + chunk) * STATE + cidx);
    float h0 = hv.x, h1 = hv.y;
    int t0 = chunk * TCH;
    size_t row0 = (size_t)b * SEQ + t0;
    float dp0 = 0.0f, dp1 = 0.0f;
    if (t0 != 0) {
        __nv_bfloat162 dv = *(const __nv_bfloat162*)(CD + (row0 - 1) * STATE + cidx);
        dp0 = __bfloat162float(dv.x); dp1 = __bfloat162float(dv.y);
    }
    for (int tl = 0; tl < TCH; tl++) {
        size_t r = (row0 + tl) * STATE + cidx;
        __nv_bfloat162 dv = *(const __nv_bfloat162*)(CD + r);
        __nv_bfloat162 uv = *(const __nv_bfloat162*)(CU2 + r);
        __nv_bfloat162 gv = *(const __nv_bfloat162*)(CGO + r);
        float d0 = __bfloat162float(dv.x), d1 = __bfloat162float(dv.y);
        float u0 = __bfloat162float(uv.x), u1 = __bfloat162float(uv.y);
        float g0 = __bfloat162float(gv.x), g1 = __bfloat162float(gv.y);
        float a0 = 1.0f - dp0, a1 = 1.0f - dp1;
        dp0 = d0; dp1 = d1;
        h0 = a0 * h0 + u0 * d0;
        h1 = a1 * h1 + u1 * d1;
        *(__nv_bfloat162*)(out1 + r) = __floats2bfloat162_rn(h0 * g0, h1 * g1);
    }
}

// ---------------- Launch ----------------
extern "C" void kernel_launch(void* const* d_in, const int* in_sizes, int n_in,
                              void* d_out, int out_size) {
    const float* x    = (const float*)d_in[0];
    const float* ls   = (const float*)d_in[1];
    const float* rs   = (const float*)d_in[2];
    const float* ss   = (const float*)d_in[3];
    const float* Wk   = (const float*)d_in[4];
    const float* Wugg = (const float*)d_in[5];
    const float* Wout = (const float*)d_in[6];
    float* y = (float*)d_out;

    __nv_bfloat16 *p_xn, *p_WT, *p_WoutT, *p_out1, *p_CD, *p_CU2, *p_CGO;
    float *p_chA, *p_chB, *p_hin;
    cudaGetSymbolAddress((void**)&p_xn,    g_xn);
    cudaGetSymbolAddress((void**)&p_WT,    g_WT);
    cudaGetSymbolAddress((void**)&p_WoutT, g_WoutT);
    cudaGetSymbolAddress((void**)&p_CD,    g_CD);
    cudaGetSymbolAddress((void**)&p_CU2,   g_CU2);
    cudaGetSymbolAddress((void**)&p_CGO,   g_CGO);
    cudaGetSymbolAddress((void**)&p_out1,  g_out1);
    cudaGetSymbolAddress((void**)&p_chA,   g_chA);
    cudaGetSymbolAddress((void**)&p_chB,   g_chB);
    cudaGetSymbolAddress((void**)&p_hin,   g_hin);

    cudaFuncSetAttribute(gemm_bf16, cudaFuncAttributeMaxDynamicSharedMemorySize, GEMM_SMEM);

    dim3 blk(32, 8);

    rmsnorm_kernel<<<ROWS, 256>>>(x, ls, rs, ss, p_xn);
    prep_WT<<<dim3(2048/32, 1024/32, 4), blk>>>(Wk, Wugg, p_WT);
    transpose_bf16<<<dim3(1024/32, 2048/32), blk>>>(Wout, p_WoutT, 2048, 1024);
    // global launch index 5 -> ncu profiles GEMM1
    gemm_bf16<<<dim3(NTOT/128, ROWS/128), 128, GEMM_SMEM>>>(
        p_xn, p_WT, NTOT, DIMS, DIMS/BK, 0,
        p_CD, p_CU2, p_CGO, nullptr, nullptr);

    // Vectorized scan: 2 channels per thread
    scan_phase1<<<dim3(STATE/512, NCH, BATCH), 256>>>(p_CD, p_CU2, p_chA, p_chB);
    scan_phase2<<<(BATCH*STATE/2)/256, 256>>>(p_chA, p_chB, p_hin);
    scan_phase3<<<dim3(STATE/512, NCH, BATCH), 256>>>(p_CD, p_CU2, p_CGO, p_hin, p_out1);

    gemm_bf16<<<dim3(DIMS/128, ROWS/128), 128, GEMM_SMEM>>>(
        p_out1, p_WoutT, DIMS, STATE, STATE/BK, 1,
        nullptr, nullptr, nullptr, y, x);
}

// round 17
// speedup vs baseline: 1.1817x; 1.0076x over previous
#include <cuda_runtime.h>
#include <cuda_bf16.h>
#include <math.h>
#include <stdint.h>

// ---------------- Problem constants ----------------
#define BATCH   4
#define SEQ     2048
#define ROWS    (BATCH*SEQ)      // 8192
#define DIMS    1024
#define STATE   2048             // 2*DIMS
#define NTOT    (4*STATE)        // 8192 logical GEMM1 columns [K | u/gin 8-blocked | gout]
#define TCH     128              // scan chunk length
#define NCH     (SEQ/TCH)        // 16 chunks

// ---------------- Scratch (device globals; no allocation allowed) ----------------
__device__ __nv_bfloat16 g_xn[(size_t)ROWS*DIMS];       // 16MB  normalized input (bf16)
__device__ __nv_bfloat16 g_WT[(size_t)NTOT*DIMS];       // 16MB  packed weights^T bf16
__device__ __nv_bfloat16 g_WoutT[(size_t)DIMS*STATE];   // 4MB   Wout^T as [n,k] bf16
__device__ __nv_bfloat16 g_CD [(size_t)ROWS*STATE];     // 32MB  d = 1-sig(K) bf16
__device__ __nv_bfloat16 g_CU2[(size_t)ROWS*STATE];     // 32MB  u2 = u*sig(gin) bf16
__device__ __nv_bfloat16 g_CGO[(size_t)ROWS*STATE];     // 32MB  sig(gout) bf16
__device__ __nv_bfloat16 g_out1[(size_t)ROWS*STATE];    // 32MB  h*sig(gout) bf16
__device__ float g_chA[BATCH*NCH*STATE];
__device__ float g_chB[BATCH*NCH*STATE];
__device__ float g_hin[BATCH*NCH*STATE];

// ---------------- Helpers ----------------
__device__ __forceinline__ uint32_t smem_u32(const void* p) {
    uint32_t a;
    asm("{ .reg .u64 t; cvta.to.shared.u64 t, %1; cvt.u32.u64 %0, t; }" : "=r"(a) : "l"(p));
    return a;
}
__device__ __forceinline__ void cp16(uint32_t dst, const void* src) {
    asm volatile("cp.async.cg.shared.global [%0], [%1], 16;" :: "r"(dst), "l"(src) : "memory");
}
#define CP_COMMIT() asm volatile("cp.async.commit_group;" ::: "memory")

__device__ __forceinline__ void ldm_x4(uint32_t* r, uint32_t addr) {
    asm volatile("ldmatrix.sync.aligned.m8n8.x4.shared.b16 {%0,%1,%2,%3}, [%4];"
                 : "=r"(r[0]), "=r"(r[1]), "=r"(r[2]), "=r"(r[3]) : "r"(addr));
}
__device__ __forceinline__ void mma_bf16(float* c, const uint32_t* a,
                                         uint32_t b0, uint32_t b1) {
    asm volatile(
        "mma.sync.aligned.m16n8k16.row.col.f32.bf16.bf16.f32 "
        "{%0,%1,%2,%3},{%4,%5,%6,%7},{%8,%9},{%0,%1,%2,%3};"
        : "+f"(c[0]), "+f"(c[1]), "+f"(c[2]), "+f"(c[3])
        : "r"(a[0]), "r"(a[1]), "r"(a[2]), "r"(a[3]), "r"(b0), "r"(b1));
}
// Fast sigmoid: MUFU.EX2-based exp + MUFU.RCP division (~4 SASS ops).
__device__ __forceinline__ float sigm(float v) {
    return __fdividef(1.0f, 1.0f + __expf(-v));
}

// ---------------- Fused prep: rmsnorm + weight packing + Wout transpose, ONE launch ----------------
// blocks [0, 8192):               rmsnorm row = bid
// blocks [8192, 16384):           prep_WT (z = (bid-8192)>>11; 64 x-blocks x 32 y-blocks)
// blocks [16384, 18432):          Wout transpose (32 x-blocks x 64 y-blocks)
__global__ void __launch_bounds__(256)
prep_all(const float* __restrict__ x,
         const float* __restrict__ ls, const float* __restrict__ rs,
         const float* __restrict__ ss,
         const float* __restrict__ Wk, const float* __restrict__ Wugg,
         const float* __restrict__ Wout,
         __nv_bfloat16* __restrict__ xn, __nv_bfloat16* __restrict__ WT,
         __nv_bfloat16* __restrict__ WoutT) {
    __shared__ float shbuf[32 * 33];
    const int bid = blockIdx.x;
    const int tid = threadIdx.x;

    if (bid < ROWS) {
        // ---- RMS split norm -> bf16 ----
        float* wsum = shbuf;
        int row = bid;
        const float* xr = x + (size_t)row * DIMS;
        float4 xv = ((const float4*)xr)[tid];
        float s = xv.x*xv.x + xv.y*xv.y + xv.z*xv.z + xv.w*xv.w;
        #pragma unroll
        for (int o = 16; o; o >>= 1) s += __shfl_xor_sync(0xffffffffu, s, o);
        if ((tid & 31) == 0) wsum[tid >> 5] = s;
        __syncthreads();
        int half = tid >> 7;
        float tot = wsum[half*4+0] + wsum[half*4+1] + wsum[half*4+2] + wsum[half*4+3];
        float n = sqrtf(tot) * 0.04419417382415922f + 1e-8f;   // 1/sqrt(512)
        float inv = 1.0f / n;
        const float* sc = half ? rs : ls;
        int jb = (tid*4) & 511;
        float4 scv = ((const float4*)sc)[jb >> 2];
        float4 ssv = ((const float4*)ss)[tid];
        __nv_bfloat162 p0 = __floats2bfloat162_rn(xv.x * scv.x * inv * ssv.x,
                                                  xv.y * scv.y * inv * ssv.y);
        __nv_bfloat162 p1 = __floats2bfloat162_rn(xv.z * scv.z * inv * ssv.z,
                                                  xv.w * scv.w * inv * ssv.w);
        __nv_bfloat162* dst = (__nv_bfloat162*)(xn + (size_t)row * DIMS);
        dst[tid*2]   = p0;
        dst[tid*2+1] = p1;
    } else if (bid < 2*ROWS) {
        // ---- Weight prep with u/gin 8-col interleave ----
        float (*tile)[33] = (float(*)[33])shbuf;
        int b  = bid - ROWS;
        int z  = b >> 11;              // 0..3
        int rem = b & 2047;
        int bx = rem & 63;             // 64 col-blocks (2048 cols)
        int by = rem >> 6;             // 32 row-blocks (1024 rows)
        const float* src = (z == 0) ? Wk : (Wugg + (z - 1) * 2048);
        int srcLD = (z == 0) ? 2048 : 6144;
        int r0 = by * 32, c0 = bx * 32;
        int tx = tid & 31, ty = tid >> 5;    // 32 x 8
        #pragma unroll
        for (int i = 0; i < 32; i += 8)
            tile[ty+i][tx] = src[(size_t)(r0+ty+i)*srcLD + c0 + tx];
        __syncthreads();
        #pragma unroll
        for (int i = 0; i < 32; i += 8) {
            int c = c0 + ty + i;
            int dstRow;
            if      (z == 0) dstRow = c;
            else if (z == 1) dstRow = 2048 + 16*(c >> 3) + (c & 7);
            else if (z == 2) dstRow = 2048 + 16*(c >> 3) + 8 + (c & 7);
            else             dstRow = 6144 + c;
            WT[(size_t)dstRow*1024 + r0 + tx] = __float2bfloat16_rn(tile[tx][ty+i]);
        }
    } else {
        // ---- Wout transpose: src [2048,1024] -> dst [1024,2048] ----
        float (*tile)[33] = (float(*)[33])shbuf;
        int b  = bid - 2*ROWS;
        int bx = b & 31;               // 32 col-blocks (1024 cols)
        int by = b >> 5;               // 64 row-blocks (2048 rows)
        int r0 = by * 32, c0 = bx * 32;
        int tx = tid & 31, ty = tid >> 5;
        #pragma unroll
        for (int i = 0; i < 32; i += 8)
            tile[ty+i][tx] = Wout[(size_t)(r0+ty+i)*1024 + c0 + tx];
        __syncthreads();
        #pragma unroll
        for (int i = 0; i < 32; i += 8)
            WoutT[(size_t)(c0+ty+i)*2048 + r0 + tx] = __float2bfloat16_rn(tile[tx][ty+i]);
    }
}

// ---------------- Legacy-MMA bf16 GEMM: CTA 128x128, 4 warps of 64x64, 2 CTA/SM ----------------
// R14 version, measured fast — FROZEN (XOR swizzle, 128B rows).
#define BK 64
#define NST 3
#define AST (128*BK*2)         // 16384 bytes per A stage
#define BST (128*BK*2)         // 16384 bytes per B stage
#define GEMM_SMEM (NST*(AST+BST))   // 98304 = 96KB

__global__ void __launch_bounds__(128, 2)
gemm_bf16(const __nv_bfloat16* __restrict__ A, const __nv_bfloat16* __restrict__ B,
          int N, int K, int NIT, int mode,
          __nv_bfloat16* __restrict__ pD, __nv_bfloat16* __restrict__ pU2,
          __nv_bfloat16* __restrict__ pGO,
          float* __restrict__ Cout, const float* __restrict__ resid) {
    extern __shared__ char smraw[];
    const uint32_t sbase = smem_u32(smraw);

    const int tid  = threadIdx.x;          // 0..127
    const int wid  = tid >> 5;             // 0..3
    const int lane = tid & 31;
    const int m0 = blockIdx.y * 128;
    const int n0 = blockIdx.x * 128;
    const int wm0 = (wid >> 1) * 64;       // warp row origin (0/64)
    const int wn0 = (wid & 1) * 64;        // warp col origin (0/64)
    const int blk = lane >> 3;             // 0..3
    const int lr8 = lane & 7;
    const int kb2 = (blk >> 1) * 16;       // +16B for k8..15 half

    // Hoisted fill addressing: 128 threads cover 16 rows/sweep, 8 sweeps per tile
    uint32_t sOff[8];
    uint32_t goA[8], goB[8];
    {
        int r = tid >> 3, c = tid & 7;
        #pragma unroll
        for (int i = 0; i < 8; i++) {
            int rr = r + i * 16;
            sOff[i] = (uint32_t)(rr * 128 + ((c ^ (rr & 7)) << 4));
            goA[i] = (uint32_t)((m0 + rr) * K + c * 8);
            goB[i] = (uint32_t)((n0 + rr) * K + c * 8);
        }
    }

    uint32_t offA[4], xrA[4], offB[4], xrB[4];
    #pragma unroll
    for (int mt = 0; mt < 4; mt++) {
        int r = wm0 + mt*16 + (blk & 1)*8 + lr8;
        offA[mt] = (uint32_t)r * 128u;
        xrA[mt]  = (uint32_t)(r & 7) << 4;
    }
    #pragma unroll
    for (int np = 0; np < 4; np++) {
        int r = wn0 + np*16 + (blk & 1)*8 + lr8;
        offB[np] = (uint32_t)r * 128u;
        xrB[np]  = (uint32_t)(r & 7) << 4;
    }

    float c[4][8][4];
    #pragma unroll
    for (int i = 0; i < 4; i++)
        #pragma unroll
        for (int j = 0; j < 8; j++)
            #pragma unroll
            for (int e = 0; e < 4; e++) c[i][j][e] = 0.0f;

    // Prologue: fill all 3 stages
    #pragma unroll
    for (int pf = 0; pf < NST; ++pf) {
        const uint32_t aS = sbase + pf*(AST+BST);
        const uint32_t bS = aS + AST;
        const uint32_t k0 = pf * BK;
        #pragma unroll
        for (int i = 0; i < 8; i++) cp16(aS + sOff[i], A + goA[i] + k0);
        #pragma unroll
        for (int i = 0; i < 8; i++) cp16(bS + sOff[i], B + goB[i] + k0);
        CP_COMMIT();
    }

    for (int it = 0; it < NIT; ++it) {
        const int s = it % NST;
        const uint32_t aS = sbase + s*(AST+BST);
        const uint32_t bS = aS + AST;

        int rem = NIT - 1 - it;
        if (rem >= 2)      asm volatile("cp.async.wait_group 2;" ::: "memory");
        else if (rem == 1) asm volatile("cp.async.wait_group 1;" ::: "memory");
        else               asm volatile("cp.async.wait_group 0;" ::: "memory");
        __syncthreads();

        #pragma unroll
        for (int kk = 0; kk < 4; ++kk) {
            uint32_t a[4][4], b[4][4];
            const uint32_t kbase = (uint32_t)(kk*32) + kb2;
            #pragma unroll
            for (int mt = 0; mt < 4; mt++)
                ldm_x4(a[mt], aS + offA[mt] + (kbase ^ xrA[mt]));
            #pragma unroll
            for (int np = 0; np < 4; np++)
                ldm_x4(b[np], bS + offB[np] + (kbase ^ xrB[np]));
            #pragma unroll
            for (int mt = 0; mt < 4; mt++)
                #pragma unroll
                for (int nt = 0; nt < 8; nt++) {
                    int np = nt >> 1, odd = nt & 1;
                    mma_bf16(c[mt][nt], a[mt], b[np][odd], b[np][2 + odd]);
                }
        }
        __syncthreads();   // everyone done reading stage s

        if (it + 3 < NIT) {
            const uint32_t k0 = (it + 3) * BK;
            #pragma unroll
            for (int i = 0; i < 8; i++) cp16(aS + sOff[i], A + goA[i] + k0);
            #pragma unroll
            for (int i = 0; i < 8; i++) cp16(bS + sOff[i], B + goB[i] + k0);
            CP_COMMIT();
        }
    }

    // Epilogue (R14, frozen)
    const int g = lane >> 2, tig = lane & 3;
    if (mode == 0) {
        if (n0 < 2048) {
            #pragma unroll
            for (int mt = 0; mt < 4; mt++) {
                int row = m0 + wm0 + mt*16 + g;
                #pragma unroll
                for (int nt = 0; nt < 8; nt++) {
                    int st = n0 + wn0 + nt*8 + 2*tig;
                    float d0 = sigm(-c[mt][nt][0]), d1 = sigm(-c[mt][nt][1]);
                    float d2 = sigm(-c[mt][nt][2]), d3 = sigm(-c[mt][nt][3]);
                    *(__nv_bfloat162*)(pD + (size_t)row * STATE + st)
                        = __floats2bfloat162_rn(d0, d1);
                    *(__nv_bfloat162*)(pD + (size_t)(row+8) * STATE + st)
                        = __floats2bfloat162_rn(d2, d3);
                }
            }
        } else if (n0 < 6144) {
            const int sbase0 = ((n0 - 2048) + wn0) >> 1;
            #pragma unroll
            for (int mt = 0; mt < 4; mt++) {
                int row = m0 + wm0 + mt*16 + g;
                #pragma unroll
                for (int j = 0; j < 4; j++) {
                    const int nte = 2*j, nto = 2*j + 1;
                    int st = sbase0 + j*8 + 2*tig;
                    float u20 = c[mt][nte][0] * sigm(c[mt][nto][0]);
                    float u21 = c[mt][nte][1] * sigm(c[mt][nto][1]);
                    float u22 = c[mt][nte][2] * sigm(c[mt][nto][2]);
                    float u23 = c[mt][nte][3] * sigm(c[mt][nto][3]);
                    *(__nv_bfloat162*)(pU2 + (size_t)row * STATE + st)
                        = __floats2bfloat162_rn(u20, u21);
                    *(__nv_bfloat162*)(pU2 + (size_t)(row+8) * STATE + st)
                        = __floats2bfloat162_rn(u22, u23);
                }
            }
        } else {
            #pragma unroll
            for (int mt = 0; mt < 4; mt++) {
                int row = m0 + wm0 + mt*16 + g;
                #pragma unroll
                for (int nt = 0; nt < 8; nt++) {
                    int st = (n0 - 6144) + wn0 + nt*8 + 2*tig;
                    float v0 = sigm(c[mt][nt][0]), v1 = sigm(c[mt][nt][1]);
                    float v2 = sigm(c[mt][nt][2]), v3 = sigm(c[mt][nt][3]);
                    *(__nv_bfloat162*)(pGO + (size_t)row * STATE + st)
                        = __floats2bfloat162_rn(v0, v1);
                    *(__nv_bfloat162*)(pGO + (size_t)(row+8) * STATE + st)
                        = __floats2bfloat162_rn(v2, v3);
                }
            }
        }
    } else {
        #pragma unroll
        for (int mt = 0; mt < 4; mt++) {
            int row = m0 + wm0 + mt*16 + g;
            #pragma unroll
            for (int nt = 0; nt < 8; nt++) {
                int col = n0 + wn0 + nt*8 + 2*tig;
                float v0 = c[mt][nt][0] + resid[(size_t)row * N + col];
                float v1 = c[mt][nt][1] + resid[(size_t)row * N + col + 1];
                float v2 = c[mt][nt][2] + resid[(size_t)(row+8) * N + col];
                float v3 = c[mt][nt][3] + resid[(size_t)(row+8) * N + col + 1];
                *(float2*)(Cout + (size_t)row * N + col)     = make_float2(v0, v1);
                *(float2*)(Cout + (size_t)(row+8) * N + col) = make_float2(v2, v3);
            }
        }
    }
}

// ---------------- Chunked linear-recurrence scan (R14 scalar, measured best) ----------------
// a_t = 1 - d_{t-1}; u'_t = u2_t * d_t; h_t = a_t h_{t-1} + u'_t
__global__ void scan_phase1(const __nv_bfloat16* __restrict__ CD,
                            const __nv_bfloat16* __restrict__ CU2,
                            float* __restrict__ chA, float* __restrict__ chB) {
    int cidx  = blockIdx.x * blockDim.x + threadIdx.x;   // 0..2047
    int chunk = blockIdx.y;
    int b     = blockIdx.z;
    float Aacc = 1.0f, Bacc = 0.0f;
    int t0 = chunk * TCH;
    size_t row0 = (size_t)b * SEQ + t0;
    float dprev = (t0 == 0) ? 0.0f : __bfloat162float(CD[(row0 - 1) * STATE + cidx]);
    for (int tl = 0; tl < TCH; tl++) {
        size_t r = (row0 + tl) * STATE + cidx;
        float d  = __bfloat162float(CD[r]);
        float u2 = __bfloat162float(CU2[r]);
        float a  = 1.0f - dprev;
        dprev = d;
        float up = u2 * d;
        Aacc = a * Aacc;
        Bacc = a * Bacc + up;
    }
    int idx = (b * NCH + chunk) * STATE + cidx;
    chA[idx] = Aacc;
    chB[idx] = Bacc;
}

__global__ void scan_phase2(const float* __restrict__ chA,
                            const float* __restrict__ chB,
                            float* __restrict__ hin) {
    int i = blockIdx.x * blockDim.x + threadIdx.x;   // b*2048+c
    int b = i >> 11, cidx = i & 2047;
    float h = 0.0f;
    for (int ch = 0; ch < NCH; ch++) {
        int idx = (b * NCH + ch) * STATE + cidx;
        hin[idx] = h;
        h = chA[idx] * h + chB[idx];
    }
}

__global__ void scan_phase3(const __nv_bfloat16* __restrict__ CD,
                            const __nv_bfloat16* __restrict__ CU2,
                            const __nv_bfloat16* __restrict__ CGO,
                            const float* __restrict__ hin,
                            __nv_bfloat16* __restrict__ out1) {
    int cidx  = blockIdx.x * blockDim.x + threadIdx.x;
    int chunk = blockIdx.y;
    int b     = blockIdx.z;
    float h = hin[(b * NCH + chunk) * STATE + cidx];
    int t0 = chunk * TCH;
    size_t row0 = (size_t)b * SEQ + t0;
    float dprev = (t0 == 0) ? 0.0f : __bfloat162float(CD[(row0 - 1) * STATE + cidx]);
    for (int tl = 0; tl < TCH; tl++) {
        size_t r = (row0 + tl) * STATE + cidx;
        float d  = __bfloat162float(CD[r]);
        float u2 = __bfloat162float(CU2[r]);
        float go = __bfloat162float(CGO[r]);
        float a  = 1.0f - dprev;
        dprev = d;
        h = a * h + u2 * d;
        out1[r] = __float2bfloat16_rn(h * go);
    }
}

// ---------------- Launch ----------------
extern "C" void kernel_launch(void* const* d_in, const int* in_sizes, int n_in,
                              void* d_out, int out_size) {
    const float* x    = (const float*)d_in[0];
    const float* ls   = (const float*)d_in[1];
    const float* rs   = (const float*)d_in[2];
    const float* ss   = (const float*)d_in[3];
    const float* Wk   = (const float*)d_in[4];
    const float* Wugg = (const float*)d_in[5];
    const float* Wout = (const float*)d_in[6];
    float* y = (float*)d_out;

    __nv_bfloat16 *p_xn, *p_WT, *p_WoutT, *p_out1, *p_CD, *p_CU2, *p_CGO;
    float *p_chA, *p_chB, *p_hin;
    cudaGetSymbolAddress((void**)&p_xn,    g_xn);
    cudaGetSymbolAddress((void**)&p_WT,    g_WT);
    cudaGetSymbolAddress((void**)&p_WoutT, g_WoutT);
    cudaGetSymbolAddress((void**)&p_CD,    g_CD);
    cudaGetSymbolAddress((void**)&p_CU2,   g_CU2);
    cudaGetSymbolAddress((void**)&p_CGO,   g_CGO);
    cudaGetSymbolAddress((void**)&p_out1,  g_out1);
    cudaGetSymbolAddress((void**)&p_chA,   g_chA);
    cudaGetSymbolAddress((void**)&p_chB,   g_chB);
    cudaGetSymbolAddress((void**)&p_hin,   g_hin);

    cudaFuncSetAttribute(gemm_bf16, cudaFuncAttributeMaxDynamicSharedMemorySize, GEMM_SMEM);

    // ONE fused prep launch: rmsnorm (8192) + weight pack (8192) + Wout transpose (2048)
    prep_all<<<2*ROWS + 2048, 256>>>(x, ls, rs, ss, Wk, Wugg, Wout,
                                     p_xn, p_WT, p_WoutT);

    // GEMM1 (frozen R14)
    gemm_bf16<<<dim3(NTOT/128, ROWS/128), 128, GEMM_SMEM>>>(
        p_xn, p_WT, NTOT, DIMS, DIMS/BK, 0,
        p_CD, p_CU2, p_CGO, nullptr, nullptr);

    // Scan (R14 scalar, measured best)
    scan_phase1<<<dim3(STATE/256, NCH, BATCH), 256>>>(p_CD, p_CU2, p_chA, p_chB);
    scan_phase2<<<(BATCH*STATE)/256, 256>>>(p_chA, p_chB, p_hin);
    scan_phase3<<<dim3(STATE/256, NCH, BATCH), 256>>>(p_CD, p_CU2, p_CGO, p_hin, p_out1);

    // GEMM2: y = out1 @ Wout + x
    gemm_bf16<<<dim3(DIMS/128, ROWS/128), 128, GEMM_SMEM>>>(
        p_out1, p_WoutT, DIMS, STATE, STATE/BK, 1,
        nullptr, nullptr, nullptr, y, x);
}